// round 3
// baseline (speedup 1.0000x reference)
#include <cuda_runtime.h>

#define FULL 0xffffffffu

constexpr int N_ = 256;
constexpr int T_ = 2000;
constexpr int K_ = 16;
constexpr int PF = 8;   // chunk / prefetch depth

// per-step linear-domain normalizers Z[t] (scratch; 2 MB)
__device__ float g_Z[N_ * T_];

// 16-term dot product: 4 parallel accumulators + 2-level tree (chain ~6 FLOP deep)
__device__ __forceinline__ float dot16(const float* __restrict__ w, float v) {
    float s0 = 0.f, s1 = 0.f, s2 = 0.f, s3 = 0.f;
#pragma unroll
    for (int i = 0; i < 4; i++) {
        s0 = fmaf(w[i],      __shfl_sync(FULL, v, i,      16), s0);
        s1 = fmaf(w[i + 4],  __shfl_sync(FULL, v, i + 4,  16), s1);
        s2 = fmaf(w[i + 8],  __shfl_sync(FULL, v, i + 8,  16), s2);
        s3 = fmaf(w[i + 12], __shfl_sync(FULL, v, i + 12, 16), s3);
    }
    return (s0 + s1) + (s2 + s3);
}

__global__ __launch_bounds__(32, 1) void hmm_fb_kernel(
    const float* __restrict__ ev,   // (N, T, K)
    const float* __restrict__ pi,   // (K)
    const float* __restrict__ Q,    // (K, K) row-stochastic
    float* __restrict__ out)        // (N, T, K) -> gamma (alpha staged here too)
{
    const int lane = threadIdx.x;
    const int j    = lane & 15;     // state index
    const int h    = lane >> 4;     // sequence half of warp
    const int n    = blockIdx.x * 2 + h;

    // Qrow[i] = Q[j][i] (backward), Qcol[i] = Q[i][j] (forward)
    float Qrow[16], Qcol[16];
#pragma unroll
    for (int i = 0; i < 16; i++) {
        Qrow[i] = Q[j * 16 + i];
        Qcol[i] = Q[i * 16 + j];
    }

    const float* evn  = ev  + (size_t)n * T_ * K_;
    float*       outn = out + (size_t)n * T_ * K_;
    float*       Zn   = g_Z + (size_t)n * T_;

    // ---------------- t = 0 ----------------
    float a;       // carried alpha (scaled by unknown-but-tracked factor c)
    float zfac;    // true Z[t] = S_measured[t] * zfac   (zfac = 1/c)
    {
        float ap = __expf(evn[j]) * pi[j];
        float S = ap;
#pragma unroll
        for (int m = 1; m < 16; m <<= 1) S += __shfl_xor_sync(FULL, S, m, 16);
        float inv = __fdividef(1.f, S);
        a = ap * inv;
        zfac = 1.f;
        outn[j] = a;
        if (j == 0) Zn[0] = S;
    }

    // ---------------- forward: t = 1 .. T-1 ----------------
    {
        float rq = 1.f, Sq = 1.f;   // stale rescale factor (=1/S from 3 steps back) + its S
        float evbuf[PF];
#pragma unroll
        for (int p = 0; p < PF; p++) {
            int t = 1 + p;
            evbuf[p] = (t < T_) ? __expf(evn[t * K_ + j]) : 0.f;
        }

        for (int tb = 1; tb < T_; tb += PF) {
            float evnext[PF];
#pragma unroll
            for (int p = 0; p < PF; p++) {
                int t = tb + PF + p;
                evnext[p] = (t < T_) ? __expf(evn[t * K_ + j]) : 0.f;
            }

#pragma unroll
            for (int p = 0; p < PF; p++) {
                int t = tb + p;
                if (t >= T_) break;
                // ---- critical chain: a -> shfl gather -> FMA tree -> mul ----
                float ap = evbuf[p] * dot16(Qcol, a);
                // periodic anti-underflow rescale by STALE factor (chain: 1 mul)
                a = (p == PF - 1) ? ap * rq : ap;

                // ---- off-chain: reduction, Z, stores, zfac bookkeeping ----
                float S = ap;
#pragma unroll
                for (int m = 1; m < 16; m <<= 1) S += __shfl_xor_sync(FULL, S, m, 16);
                float inv = __fdividef(1.f, S);
                if (j == 0) Zn[t] = S * zfac;
                outn[t * K_ + j] = ap * inv;     // normalized alpha[t]
                // scale entering next step: c' = r*S  =>  zfac' = inv * (1/r)
                zfac = (p == PF - 1) ? inv * Sq : inv;
                if (p == PF - 4) { rq = inv; Sq = S; }  // stage stale rescale factor
            }
#pragma unroll
            for (int p = 0; p < PF; p++) evbuf[p] = evnext[p];
        }
    }

    // ---------------- backward: t = T-1 .. 1, then t = 0 ----------------
    {
        float b = 1.f;              // scaled beta[T-1] = 1
        float elz[PF];              // exp(ev[t]) / Z[t]
        float alb[PF];              // normalized alpha[t]
#pragma unroll
        for (int p = 0; p < PF; p++) {
            int t = T_ - 1 - p;
            elz[p] = __expf(evn[t * K_ + j]) * __fdividef(1.f, Zn[t]);
            alb[p] = outn[t * K_ + j];
        }

        for (int tb = T_ - 1; tb >= 1; tb -= PF) {
            float elz2[PF], alb2[PF];
#pragma unroll
            for (int p = 0; p < PF; p++) {
                int t = tb - PF - p;
                bool ok = (t >= 1);
                elz2[p] = ok ? (__expf(evn[t * K_ + j]) * __fdividef(1.f, Zn[t])) : 0.f;
                alb2[p] = ok ? outn[t * K_ + j] : 0.f;
            }

#pragma unroll
            for (int p = 0; p < PF; p++) {
                int t = tb - p;
                if (t < 1) break;
                // gamma[t] = alpha[t] * beta[t]   (off-chain store)
                outn[t * K_ + j] = alb[p] * b;
                // critical chain: b -> mul -> shfl gather -> FMA tree -> b
                b = dot16(Qrow, elz[p] * b);
            }
#pragma unroll
            for (int p = 0; p < PF; p++) { elz[p] = elz2[p]; alb[p] = alb2[p]; }
        }

        // t = 0: gamma[0] = alpha[0] * beta[0]
        outn[j] = outn[j] * b;
    }
}

extern "C" void kernel_launch(void* const* d_in, const int* in_sizes, int n_in,
                              void* d_out, int out_size) {
    const float* ev = (const float*)d_in[0];   // local_evidence (N,T,K)
    const float* pi = (const float*)d_in[1];   // (K)
    const float* Q  = (const float*)d_in[2];   // (K,K)
    float* out = (float*)d_out;
    hmm_fb_kernel<<<N_ / 2, 32>>>(ev, pi, Q, out);
}

// round 5
// speedup vs baseline: 1.5057x; 1.5057x over previous
#include <cuda_runtime.h>

#define FULL 0xffffffffu

constexpr int N_ = 256;
constexpr int T_ = 2000;
constexpr int K_ = 16;
constexpr int PF = 8;

// raw (arbitrarily scaled) beta scratch, 32 MB
__device__ float g_B[(size_t)N_ * T_ * K_];

__global__ __launch_bounds__(32, 1) void hmm_recur_kernel(
    const float* __restrict__ ev,   // (N, T, K)
    const float* __restrict__ pi,   // (K)
    const float* __restrict__ Q,    // (K, K)
    float* __restrict__ out)        // (N, T, K): raw alpha staged here
{
    const int lane = threadIdx.x;
    const int j    = lane & 15;
    const int h    = lane >> 4;
    const bool bwd = blockIdx.x >= (N_ / 2);
    const int n    = ((int)blockIdx.x & (N_ / 2 - 1)) * 2 + h;

    const float* evn = ev + (size_t)n * T_ * K_ + j;   // lane-local base

    if (!bwd) {
        // ================= FORWARD: raw alpha =================
        float Qcol[16];
#pragma unroll
        for (int i = 0; i < 16; i++) Qcol[i] = Q[i * 16 + j];
        float* an = out + (size_t)n * T_ * K_ + j;

        float a = __expf(evn[0]) * pi[j];
        an[0] = a;

        float rq = 1.f;
        float eb[PF];
#pragma unroll
        for (int p = 0; p < PF; p++) {
            int t = 1 + p;
            eb[p] = (t < T_) ? __expf(evn[t * K_]) : 0.f;
        }

        for (int tb = 1; tb < T_; tb += PF) {
            float en[PF];
#pragma unroll
            for (int p = 0; p < PF; p++) {
                int t = tb + PF + p;
                en[p] = (t < T_) ? __expf(evn[t * K_]) : 0.f;
            }
#pragma unroll
            for (int p = 0; p < PF; p++) {
                int t = tb + p;
                if (t >= T_) break;
                float g0  = __shfl_sync(FULL, a, 0, 16),  g1  = __shfl_sync(FULL, a, 1, 16);
                float g2  = __shfl_sync(FULL, a, 2, 16),  g3  = __shfl_sync(FULL, a, 3, 16);
                float g4  = __shfl_sync(FULL, a, 4, 16),  g5  = __shfl_sync(FULL, a, 5, 16);
                float g6  = __shfl_sync(FULL, a, 6, 16),  g7  = __shfl_sync(FULL, a, 7, 16);
                float g8  = __shfl_sync(FULL, a, 8, 16),  g9  = __shfl_sync(FULL, a, 9, 16);
                float g10 = __shfl_sync(FULL, a, 10, 16), g11 = __shfl_sync(FULL, a, 11, 16);
                float g12 = __shfl_sync(FULL, a, 12, 16), g13 = __shfl_sync(FULL, a, 13, 16);
                float g14 = __shfl_sync(FULL, a, 14, 16), g15 = __shfl_sync(FULL, a, 15, 16);

                float s0 = Qcol[0] * g0, s1 = Qcol[4] * g4, s2 = Qcol[8] * g8, s3 = Qcol[12] * g12;
                s0 = fmaf(Qcol[1],  g1,  s0); s1 = fmaf(Qcol[5],  g5,  s1);
                s2 = fmaf(Qcol[9],  g9,  s2); s3 = fmaf(Qcol[13], g13, s3);
                s0 = fmaf(Qcol[2],  g2,  s0); s1 = fmaf(Qcol[6],  g6,  s1);
                s2 = fmaf(Qcol[10], g10, s2); s3 = fmaf(Qcol[14], g14, s3);
                s0 = fmaf(Qcol[3],  g3,  s0); s1 = fmaf(Qcol[7],  g7,  s1);
                s2 = fmaf(Qcol[11], g11, s2); s3 = fmaf(Qcol[15], g15, s3);
                float ap = eb[p] * ((s0 + s1) + (s2 + s3));

                if (p == PF - 4) {   // off-chain magnitude estimate, used (stale) at p==7
                    float S = (((g0 + g1) + (g2 + g3)) + ((g4 + g5) + (g6 + g7)))
                            + (((g8 + g9) + (g10 + g11)) + ((g12 + g13) + (g14 + g15)));
                    rq = __fdividef(1.f, S);
                }
                a = (p == PF - 1) ? ap * rq : ap;
                an[t * K_] = a;              // raw alpha (row-consistent scale)
            }
#pragma unroll
            for (int p = 0; p < PF; p++) eb[p] = en[p];
        }
    } else {
        // ================= BACKWARD: raw beta =================
        float Qrow[16];
#pragma unroll
        for (int i = 0; i < 16; i++) Qrow[i] = Q[j * 16 + i];
        float* bn = g_B + (size_t)n * T_ * K_ + j;

        float b = 1.f;
        bn[(T_ - 1) * K_] = 1.f;

        float rq = 1.f;
        float eb[PF];
#pragma unroll
        for (int p = 0; p < PF; p++) {
            int t = T_ - 1 - p;
            eb[p] = __expf(evn[t * K_]);
        }

        for (int tb = T_ - 1; tb >= 1; tb -= PF) {
            float en[PF];
#pragma unroll
            for (int p = 0; p < PF; p++) {
                int t = tb - PF - p;
                en[p] = (t >= 1) ? __expf(evn[t * K_]) : 0.f;
            }
#pragma unroll
            for (int p = 0; p < PF; p++) {
                int t = tb - p;
                if (t < 1) break;
                float c = eb[p] * b;
                float g0  = __shfl_sync(FULL, c, 0, 16),  g1  = __shfl_sync(FULL, c, 1, 16);
                float g2  = __shfl_sync(FULL, c, 2, 16),  g3  = __shfl_sync(FULL, c, 3, 16);
                float g4  = __shfl_sync(FULL, c, 4, 16),  g5  = __shfl_sync(FULL, c, 5, 16);
                float g6  = __shfl_sync(FULL, c, 6, 16),  g7  = __shfl_sync(FULL, c, 7, 16);
                float g8  = __shfl_sync(FULL, c, 8, 16),  g9  = __shfl_sync(FULL, c, 9, 16);
                float g10 = __shfl_sync(FULL, c, 10, 16), g11 = __shfl_sync(FULL, c, 11, 16);
                float g12 = __shfl_sync(FULL, c, 12, 16), g13 = __shfl_sync(FULL, c, 13, 16);
                float g14 = __shfl_sync(FULL, c, 14, 16), g15 = __shfl_sync(FULL, c, 15, 16);

                float s0 = Qrow[0] * g0, s1 = Qrow[4] * g4, s2 = Qrow[8] * g8, s3 = Qrow[12] * g12;
                s0 = fmaf(Qrow[1],  g1,  s0); s1 = fmaf(Qrow[5],  g5,  s1);
                s2 = fmaf(Qrow[9],  g9,  s2); s3 = fmaf(Qrow[13], g13, s3);
                s0 = fmaf(Qrow[2],  g2,  s0); s1 = fmaf(Qrow[6],  g6,  s1);
                s2 = fmaf(Qrow[10], g10, s2); s3 = fmaf(Qrow[14], g14, s3);
                s0 = fmaf(Qrow[3],  g3,  s0); s1 = fmaf(Qrow[7],  g7,  s1);
                s2 = fmaf(Qrow[11], g11, s2); s3 = fmaf(Qrow[15], g15, s3);
                float bp = (s0 + s1) + (s2 + s3);

                if (p == PF - 4) {
                    float S = (((g0 + g1) + (g2 + g3)) + ((g4 + g5) + (g6 + g7)))
                            + (((g8 + g9) + (g10 + g11)) + ((g12 + g13) + (g14 + g15)));
                    rq = __fdividef(1.f, S);
                }
                b = (p == PF - 1) ? bp * rq : bp;
                bn[(t - 1) * K_] = b;        // raw beta[t-1]
            }
#pragma unroll
            for (int p = 0; p < PF; p++) eb[p] = en[p];
        }
    }
}

// gamma = rownormalize(alpha_raw * beta_raw); 4 lanes per (n,t) row, float4 each
// N*T*4 = 2,048,000 threads = exactly 8000 blocks of 256 (no tail guard needed)
__global__ __launch_bounds__(256) void gamma_kernel(float* __restrict__ out)
{
    int idx4 = blockIdx.x * blockDim.x + threadIdx.x;   // float4 index
    float4 a = reinterpret_cast<const float4*>(out)[idx4];
    float4 b = reinterpret_cast<const float4*>(g_B)[idx4];
    float4 p;
    p.x = a.x * b.x; p.y = a.y * b.y; p.z = a.z * b.z; p.w = a.w * b.w;
    float s = (p.x + p.y) + (p.z + p.w);
    s += __shfl_xor_sync(FULL, s, 1, 4);
    s += __shfl_xor_sync(FULL, s, 2, 4);
    float inv = __fdividef(1.f, s);
    p.x *= inv; p.y *= inv; p.z *= inv; p.w *= inv;
    reinterpret_cast<float4*>(out)[idx4] = p;
}

extern "C" void kernel_launch(void* const* d_in, const int* in_sizes, int n_in,
                              void* d_out, int out_size) {
    const float* ev = (const float*)d_in[0];
    const float* pi = (const float*)d_in[1];
    const float* Q  = (const float*)d_in[2];
    float* out = (float*)d_out;
    hmm_recur_kernel<<<N_, 32>>>(ev, pi, Q, out);       // 128 fwd + 128 bwd blocks
    gamma_kernel<<<N_ * T_ * 4 / 256, 256>>>(out);
}